// round 6
// baseline (speedup 1.0000x reference)
#include <cuda_runtime.h>
#include <cuda_bf16.h>
#include <cstdint>

#define HID   256
#define NN    4096
#define BATCH 4
#define ROWS  (BATCH*NN)   // 16384
#define KNN   8
#define NCAND 16

// ---- scratch (static device globals; no runtime allocation) ----
__device__ __nv_bfloat16 d_Qh[(size_t)ROWS * HID];
__device__ __nv_bfloat16 d_Ql[(size_t)ROWS * HID];
__device__ __nv_bfloat16 d_Kh[(size_t)ROWS * HID];
__device__ __nv_bfloat16 d_Kl[(size_t)ROWS * HID];
__device__ float d_Qf[(size_t)ROWS * HID];
__device__ float d_Kf[(size_t)ROWS * HID];
__device__ float d_Sg[(size_t)BATCH * NN * NN];         // 268 MB
__device__ int   d_C16[ROWS * NCAND];
__device__ float d_Mv[ROWS];
__device__ float d_Zv[ROWS];
__device__ float d_TopV[ROWS * KNN];
__device__ int   d_TopI[ROWS * KNN];

typedef unsigned long long u64;

// ============================================================================
// PTX helpers (all sm_80-baseline)
// ============================================================================
__device__ __forceinline__ uint32_t smem_u32(const void* p) {
    uint32_t a;
    asm("{ .reg .u64 t; cvta.to.shared.u64 t, %1; cvt.u32.u64 %0, t; }" : "=r"(a) : "l"(p));
    return a;
}
__device__ __forceinline__ void cp16(uint32_t dst, const void* src) {
    asm volatile("cp.async.cg.shared.global [%0], [%1], 16;" :: "r"(dst), "l"(src));
}
__device__ __forceinline__ void ldsm4(uint32_t r[4], uint32_t addr) {
    asm volatile("ldmatrix.sync.aligned.m8n8.x4.shared.b16 {%0,%1,%2,%3}, [%4];"
                 : "=r"(r[0]), "=r"(r[1]), "=r"(r[2]), "=r"(r[3]) : "r"(addr));
}
__device__ __forceinline__ void mma_bf16(float c[4], const uint32_t a[4],
                                         uint32_t b0, uint32_t b1) {
    asm volatile(
        "mma.sync.aligned.m16n8k16.row.col.f32.bf16.bf16.f32 "
        "{%0,%1,%2,%3}, {%4,%5,%6,%7}, {%8,%9}, {%0,%1,%2,%3};"
        : "+f"(c[0]), "+f"(c[1]), "+f"(c[2]), "+f"(c[3])
        : "r"(a[0]), "r"(a[1]), "r"(a[2]), "r"(a[3]), "r"(b0), "r"(b1));
}
__device__ __forceinline__ u64 pk2(float lo, float hi) {
    u64 r;
    asm("mov.b64 %0, {%1, %2};" : "=l"(r) : "f"(lo), "f"(hi));
    return r;
}
__device__ __forceinline__ void upk2(u64 v, float& lo, float& hi) {
    asm("mov.b64 {%0, %1}, %2;" : "=f"(lo), "=f"(hi) : "l"(v));
}
__device__ __forceinline__ void fma2(u64& d, u64 a, u64 b) {
    asm("fma.rn.f32x2 %0, %1, %2, %0;" : "+l"(d) : "l"(a), "l"(b));
}
__device__ __forceinline__ uint32_t mono_f(float f) {
    uint32_t u = __float_as_uint(f);
    return (u & 0x80000000u) ? ~u : (u | 0x80000000u);
}

// ============================================================================
// Projection: O = x @ W^T + b -> fp32 copy + bf16 hi/lo split.
// ============================================================================
#define BM 128
#define BN 128
#define BK 16
#define TM 8
#define TN 8

__global__ __launch_bounds__(256, 2) void proj_kernel(
    const float* __restrict__ A, const float* __restrict__ B,
    const float* __restrict__ bias,
    float* __restrict__ Of,
    __nv_bfloat16* __restrict__ Oh, __nv_bfloat16* __restrict__ Ol)
{
    const int Kd = HID;
    const int tid = threadIdx.x;
    const int tx  = tid & 15;
    const int ty  = tid >> 4;
    const long bm = (long)blockIdx.y * BM;
    const long bn = (long)blockIdx.x * BN;

    __shared__ float As[2][BK][BM];
    __shared__ float Bs[2][BK][BN];

    u64 acc[TM][TN/2];
#pragma unroll
    for (int i = 0; i < TM; i++)
#pragma unroll
        for (int j = 0; j < TN/2; j++) acc[i][j] = 0ULL;

    const int lr = tid >> 1;
    const int lc = (tid & 1) * 8;
    const float* Abase = A + (bm + lr) * Kd + lc;
    const float* Bbase = B + (bn + lr) * Kd + lc;

    float4 ra0, ra1, rb0, rb1;
    ra0 = *(const float4*)(Abase);
    ra1 = *(const float4*)(Abase + 4);
    rb0 = *(const float4*)(Bbase);
    rb1 = *(const float4*)(Bbase + 4);
    {
        As[0][lc+0][lr]=ra0.x; As[0][lc+1][lr]=ra0.y; As[0][lc+2][lr]=ra0.z; As[0][lc+3][lr]=ra0.w;
        As[0][lc+4][lr]=ra1.x; As[0][lc+5][lr]=ra1.y; As[0][lc+6][lr]=ra1.z; As[0][lc+7][lr]=ra1.w;
        Bs[0][lc+0][lr]=rb0.x; Bs[0][lc+1][lr]=rb0.y; Bs[0][lc+2][lr]=rb0.z; Bs[0][lc+3][lr]=rb0.w;
        Bs[0][lc+4][lr]=rb1.x; Bs[0][lc+5][lr]=rb1.y; Bs[0][lc+6][lr]=rb1.z; Bs[0][lc+7][lr]=rb1.w;
    }
    __syncthreads();

    const int KT = Kd / BK;
    for (int kt = 0; kt < KT; ++kt) {
        const int buf = kt & 1;
        if (kt + 1 < KT) {
            const float* Ap = Abase + (kt + 1) * BK;
            const float* Bp = Bbase + (kt + 1) * BK;
            ra0 = *(const float4*)(Ap);  ra1 = *(const float4*)(Ap + 4);
            rb0 = *(const float4*)(Bp);  rb1 = *(const float4*)(Bp + 4);
        }
#pragma unroll
        for (int kk = 0; kk < BK; kk++) {
            float4 a0 = *(const float4*)&As[buf][kk][ty * TM];
            float4 a1 = *(const float4*)&As[buf][kk][ty * TM + 4];
            ulonglong2 b0 = *(const ulonglong2*)&Bs[buf][kk][tx * TN];
            ulonglong2 b1 = *(const ulonglong2*)&Bs[buf][kk][tx * TN + 4];
            u64 ad[TM] = {
                pk2(a0.x,a0.x), pk2(a0.y,a0.y), pk2(a0.z,a0.z), pk2(a0.w,a0.w),
                pk2(a1.x,a1.x), pk2(a1.y,a1.y), pk2(a1.z,a1.z), pk2(a1.w,a1.w)
            };
            u64 bd[4] = { b0.x, b0.y, b1.x, b1.y };
#pragma unroll
            for (int i = 0; i < TM; i++) {
                fma2(acc[i][0], ad[i], bd[0]);
                fma2(acc[i][1], ad[i], bd[1]);
                fma2(acc[i][2], ad[i], bd[2]);
                fma2(acc[i][3], ad[i], bd[3]);
            }
        }
        if (kt + 1 < KT) {
            const int nb = buf ^ 1;
            As[nb][lc+0][lr]=ra0.x; As[nb][lc+1][lr]=ra0.y; As[nb][lc+2][lr]=ra0.z; As[nb][lc+3][lr]=ra0.w;
            As[nb][lc+4][lr]=ra1.x; As[nb][lc+5][lr]=ra1.y; As[nb][lc+6][lr]=ra1.z; As[nb][lc+7][lr]=ra1.w;
            Bs[nb][lc+0][lr]=rb0.x; Bs[nb][lc+1][lr]=rb0.y; Bs[nb][lc+2][lr]=rb0.z; Bs[nb][lc+3][lr]=rb0.w;
            Bs[nb][lc+4][lr]=rb1.x; Bs[nb][lc+5][lr]=rb1.y; Bs[nb][lc+6][lr]=rb1.z; Bs[nb][lc+7][lr]=rb1.w;
        }
        __syncthreads();
    }

#pragma unroll
    for (int i = 0; i < TM; i++) {
        const long rrow = bm + ty * TM + i;
        const long cb = bn + tx * TN;
        float o[8];
        upk2(acc[i][0], o[0], o[1]);
        upk2(acc[i][1], o[2], o[3]);
        upk2(acc[i][2], o[4], o[5]);
        upk2(acc[i][3], o[6], o[7]);
        const float* bp = bias + cb;
#pragma unroll
        for (int j = 0; j < 8; j++) {
            float v = o[j] + bp[j];
            o[j] = v;
            __nv_bfloat16 h = __float2bfloat16(v);
            __nv_bfloat16 l = __float2bfloat16(v - __bfloat162float(h));
            Oh[rrow * HID + cb + j] = h;
            Ol[rrow * HID + cb + j] = l;
        }
        *(float4*)(Of + rrow * HID + cb)     = make_float4(o[0], o[1], o[2], o[3]);
        *(float4*)(Of + rrow * HID + cb + 4) = make_float4(o[4], o[5], o[6], o[7]);
    }
}

// ============================================================================
// Scores GEMM via mma.sync (bf16, error-compensated 3-pass)
// ============================================================================
#define SPITCH 40

__global__ __launch_bounds__(256) void scores_kernel()
{
    __shared__ __align__(16) __nv_bfloat16 sA[2][128 * SPITCH];
    __shared__ __align__(16) __nv_bfloat16 sB[2][128 * SPITCH];

    const int tid = threadIdx.x;
    const int wid = tid >> 5, l = tid & 31;
    const int wm = wid & 1;
    const int wn = wid >> 1;
    const long b  = blockIdx.z;
    const long bm = (long)blockIdx.y * 128;
    const long bn = (long)blockIdx.x * 128;

    const uint32_t sAu = smem_u32(sA);
    const uint32_t sBu = smem_u32(sB);

    float cacc[4][4][4];
#pragma unroll
    for (int mi = 0; mi < 4; mi++)
#pragma unroll
        for (int ni = 0; ni < 4; ni++)
#pragma unroll
            for (int e = 0; e < 4; e++) cacc[mi][ni][e] = 0.f;

    auto fill = [&](int stage, int c) {
        const int pass = c >> 3;
        const int kb   = (c & 7) * 64;
        const char* Ag = (const char*)((pass == 2 ? d_Ql : d_Qh) + (b * NN + bm) * HID) + kb;
        const char* Bg = (const char*)((pass == 1 ? d_Kl : d_Kh) + (b * NN + bn) * HID) + kb;
        const uint32_t da = sAu + stage * (128 * SPITCH * 2);
        const uint32_t db = sBu + stage * (128 * SPITCH * 2);
#pragma unroll
        for (int i = 0; i < 2; i++) {
            const int idx = tid + i * 256;
            const int row = idx >> 2, ch = idx & 3;
            cp16(da + row * (SPITCH * 2) + ch * 16, Ag + (size_t)row * (HID * 2) + ch * 16);
            cp16(db + row * (SPITCH * 2) + ch * 16, Bg + (size_t)row * (HID * 2) + ch * 16);
        }
    };

    fill(0, 0);
    asm volatile("cp.async.commit_group;" ::: "memory");
    fill(1, 1);
    asm volatile("cp.async.commit_group;" ::: "memory");

    for (int c = 0; c < 24; c++) {
        const int s = c & 1;
        if (c < 22) asm volatile("cp.async.wait_group 1;" ::: "memory");
        else        asm volatile("cp.async.wait_group 0;" ::: "memory");
        __syncthreads();

        const uint32_t ab = sAu + s * (128 * SPITCH * 2);
        const uint32_t bb = sBu + s * (128 * SPITCH * 2);

        uint32_t af[2][4][4];
        uint32_t bf[2][2][4];
        const int rA = ((l >> 3) & 1) * 8 + (l & 7);
        const int cA = (l >> 4) * 16;
        const int rB = (l >> 4) * 8 + (l & 7);
        const int cB = ((l >> 3) & 1) * 16;
#pragma unroll
        for (int kk = 0; kk < 2; kk++) {
#pragma unroll
            for (int mi = 0; mi < 4; mi++)
                ldsm4(af[kk][mi],
                      ab + (uint32_t)(wm * 64 + mi * 16 + rA) * (SPITCH * 2) + kk * 32 + cA);
#pragma unroll
            for (int bi = 0; bi < 2; bi++)
                ldsm4(bf[kk][bi],
                      bb + (uint32_t)(wn * 32 + bi * 16 + rB) * (SPITCH * 2) + kk * 32 + cB);
        }
        __syncthreads();

        if (c + 2 < 24) {
            fill(s, c + 2);
            asm volatile("cp.async.commit_group;" ::: "memory");
        }

#pragma unroll
        for (int kk = 0; kk < 2; kk++)
#pragma unroll
            for (int mi = 0; mi < 4; mi++)
#pragma unroll
                for (int ni = 0; ni < 4; ni++) {
                    const int bi = ni >> 1, p = ni & 1;
                    mma_bf16(cacc[mi][ni], af[kk][mi],
                             bf[kk][bi][p * 2], bf[kk][bi][p * 2 + 1]);
                }
    }

    const int g = l >> 2, tg = l & 3;
#pragma unroll
    for (int mi = 0; mi < 4; mi++) {
        const long r0 = bm + wm * 64 + mi * 16 + g;
        float* S0 = d_Sg + ((size_t)(b * NN + r0)) * NN + bn + wn * 32;
        float* S1 = S0 + 8 * NN;
#pragma unroll
        for (int ni = 0; ni < 4; ni++) {
            const int co = ni * 8 + tg * 2;
            float2 v0 = { cacc[mi][ni][0] * 0.0625f, cacc[mi][ni][1] * 0.0625f };
            float2 v1 = { cacc[mi][ni][2] * 0.0625f, cacc[mi][ni][3] * 0.0625f };
            *(float2*)(S0 + co) = v0;
            *(float2*)(S1 + co) = v1;
        }
    }
}

// ============================================================================
// rowtopk: single pass -> approx (m, Z) + top-16 candidate indices.
// key = (monotonic(value) << 32) | (4095 - idx)
// ============================================================================
#define CSW(x, y) do { u64 _a = (x), _b = (y); \
    (x) = _a > _b ? _a : _b; (y) = _a > _b ? _b : _a; } while (0)

__device__ __forceinline__ void clean16(u64 c[16]) {
#pragma unroll
    for (int i = 0; i < 8; i++) CSW(c[i], c[i + 8]);
#pragma unroll
    for (int g = 0; g < 2; g++)
#pragma unroll
        for (int i = 0; i < 4; i++) CSW(c[g*8 + i], c[g*8 + i + 4]);
#pragma unroll
    for (int g = 0; g < 4; g++)
#pragma unroll
        for (int i = 0; i < 2; i++) CSW(c[g*4 + i], c[g*4 + i + 2]);
#pragma unroll
    for (int g = 0; g < 8; g++) CSW(c[g*2], c[g*2 + 1]);
}
__device__ __forceinline__ void merge16_keep(u64 a[16], const u64 b[16]) {
    u64 t[16];
#pragma unroll
    for (int k = 0; k < 16; k++) {
        u64 x = a[k], y = b[15 - k];
        t[k] = x > y ? x : y;
    }
    clean16(t);
#pragma unroll
    for (int k = 0; k < 16; k++) a[k] = t[k];
}

__global__ __launch_bounds__(256) void rowtopk_kernel()
{
    const int row = blockIdx.x;
    const int tid = threadIdx.x, lid = tid & 31, wid = tid >> 5;
    const float4* S4 = (const float4*)(d_Sg + (size_t)row * NN);

    u64 a8[8];
#pragma unroll
    for (int k = 0; k < 8; k++) a8[k] = 0ULL;
    float m = -1e30f, z = 0.f;

#pragma unroll
    for (int j = 0; j < 4; j++) {
        const int p4 = tid + 256 * j;
        float4 v4 = S4[p4];
        float vv[4] = { v4.x, v4.y, v4.z, v4.w };
#pragma unroll
        for (int e = 0; e < 4; e++) {
            const float v = vv[e];
            const float nm = fmaxf(m, v);
            z = z * __expf(m - nm) + __expf(v - nm);
            m = nm;
            u64 key = ((u64)mono_f(v) << 32) | (unsigned)(4095 - (p4 * 4 + e));
            if (key > a8[7]) {
                a8[7] = key;
#pragma unroll
                for (int t2 = 7; t2 > 0; t2--)
                    if (a8[t2] > a8[t2-1]) { u64 tm = a8[t2]; a8[t2] = a8[t2-1]; a8[t2-1] = tm; }
            }
        }
    }

    // pair merge: lane^1, full sorted-16 (no loss)
    u64 c[16];
#pragma unroll
    for (int k = 0; k < 8; k++) c[k] = a8[k];
#pragma unroll
    for (int k = 0; k < 8; k++)
        c[8 + k] = __shfl_xor_sync(0xFFFFFFFFu, a8[7 - k], 1);
    clean16(c);
    {
        const float mo = __shfl_xor_sync(0xFFFFFFFFu, m, 1);
        const float zo = __shfl_xor_sync(0xFFFFFFFFu, z, 1);
        const float nm = fmaxf(m, mo);
        z = z * __expf(m - nm) + zo * __expf(mo - nm);
        m = nm;
    }

#pragma unroll
    for (int off = 2; off <= 16; off <<= 1) {
        u64 bb[16];
#pragma unroll
        for (int k = 0; k < 16; k++) bb[k] = __shfl_xor_sync(0xFFFFFFFFu, c[k], off);
        merge16_keep(c, bb);
        const float mo = __shfl_xor_sync(0xFFFFFFFFu, m, off);
        const float zo = __shfl_xor_sync(0xFFFFFFFFu, z, off);
        const float nm = fmaxf(m, mo);
        z = z * __expf(m - nm) + zo * __expf(mo - nm);
        m = nm;
    }

    __shared__ u64 cand[8][16];
    __shared__ float smx[8], szz[8];
    if (lid < 16) cand[wid][lid] = c[lid];
    if (lid == 0) { smx[wid] = m; szz[wid] = z; }
    __syncthreads();

    if (wid == 0) {
        u64 aa[16];
        if (lid < 8) {
#pragma unroll
            for (int k = 0; k < 16; k++) aa[k] = cand[lid][k];
            m = smx[lid]; z = szz[lid];
        } else {
#pragma unroll
            for (int k = 0; k < 16; k++) aa[k] = 0ULL;
            m = -1e30f; z = 0.f;
        }
#pragma unroll
        for (int off = 4; off; off >>= 1) {
            u64 bb[16];
#pragma unroll
            for (int k = 0; k < 16; k++) bb[k] = __shfl_xor_sync(0xFFFFFFFFu, aa[k], off);
            merge16_keep(aa, bb);
            const float mo = __shfl_xor_sync(0xFFFFFFFFu, m, off);
            const float zo = __shfl_xor_sync(0xFFFFFFFFu, z, off);
            const float nm = fmaxf(m, mo);
            z = z * __expf(m - nm) + zo * __expf(mo - nm);
            m = nm;
        }
        if (lid == 0) {
#pragma unroll
            for (int k = 0; k < 16; k++)
                d_C16[row * NCAND + k] = 4095 - (int)(aa[k] & 0xFFFFFFFFu);
            d_Mv[row] = m;
            d_Zv[row] = z;
        }
    }
}

// ============================================================================
// rescore: fp32 SEQUENTIAL-k fma chain — bit-identical arithmetic to the R1
// fp32 SGEMM that passed (FFMA k=0..255 ascending, then *0.0625f).
// One warp per row; lanes 0..15 each score one candidate.
// ============================================================================
__global__ __launch_bounds__(256) void rescore_kernel()
{
    __shared__ float sq[8][HID];
    const int wid = threadIdx.x >> 5, lane = threadIdx.x & 31;
    const int row = blockIdx.x * 8 + wid;
    const int b = row >> 12;

    for (int i = lane; i < HID; i += 32)
        sq[wid][i] = d_Qf[(size_t)row * HID + i];
    __syncwarp();

    float s = 0.f; int j = 0;
    if (lane < NCAND) {
        j = d_C16[row * NCAND + lane];
        const float* kr = d_Kf + ((size_t)((b << 12) + j)) * HID;
        float acc = 0.f;
#pragma unroll
        for (int k = 0; k < HID; k++)
            acc = fmaf(sq[wid][k], __ldg(kr + k), acc);
        s = acc * 0.0625f;
    }

    // gather all candidates to lane 0
    float scs[NCAND]; int ixs[NCAND];
#pragma unroll
    for (int c = 0; c < NCAND; c++) {
        scs[c] = __shfl_sync(0xFFFFFFFFu, s, c);
        ixs[c] = __shfl_sync(0xFFFFFFFFu, j, c);
    }

    if (lane == 0) {
        u64 key[NCAND];
#pragma unroll
        for (int c = 0; c < NCAND; c++)
            key[c] = ((u64)mono_f(scs[c]) << 32) | (unsigned)(4095 - ixs[c]);
        // insertion sort descending (tie -> lowest index via key low bits)
        for (int i = 1; i < NCAND; i++) {
            u64 kv = key[i];
            int jj = i;
            while (jj > 0 && key[jj-1] < kv) { key[jj] = key[jj-1]; jj--; }
            key[jj] = kv;
        }
        const float m = d_Mv[row], z = d_Zv[row];
        float ev[KNN]; int oi[KNN]; float E8 = 0.f;
#pragma unroll
        for (int k = 0; k < KNN; k++) {
            const uint32_t mv = (uint32_t)(key[k] >> 32);
            const uint32_t u = (mv & 0x80000000u) ? (mv ^ 0x80000000u) : ~mv;
            const float sv = __uint_as_float(u);
            oi[k] = 4095 - (int)(key[k] & 0xFFFFFFFFu);
            ev[k] = __expf(sv - m);
            E8 += ev[k];
        }
        const float inv = 1.0f / (E8 + 1e-6f * z);
#pragma unroll
        for (int k = 0; k < KNN; k++) {
            d_TopV[row * KNN + k] = ev[k] * inv;
            d_TopI[row * KNN + k] = oi[k];
        }
    }
}

// ============================================================================
// Output: zero then symmetric sparse scatter (0.5*(A + A^T))
// ============================================================================
__global__ void zero_kernel(float* __restrict__ out)
{
    const size_t i = (size_t)blockIdx.x * blockDim.x + threadIdx.x;
    ((float4*)out)[i] = make_float4(0.f, 0.f, 0.f, 0.f);
}

__global__ void scatter_kernel(float* __restrict__ out)
{
    const int t = blockIdx.x * blockDim.x + threadIdx.x;
    if (t >= ROWS * KNN) return;
    const int row = t / KNN;
    const int b = row >> 12;
    const int i = row & (NN - 1);
    const int j = d_TopI[t];
    const float v = 0.5f * d_TopV[t];
    float* base = out + (size_t)b * NN * NN;
    atomicAdd(base + (size_t)i * NN + j, v);
    atomicAdd(base + (size_t)j * NN + i, v);
}

// ============================================================================
extern "C" void kernel_launch(void* const* d_in, const int* in_sizes, int n_in,
                              void* d_out, int out_size)
{
    const float* x  = (const float*)d_in[0];
    const float* Wq = (const float*)d_in[1];
    const float* bq = (const float*)d_in[2];
    const float* Wk = (const float*)d_in[3];
    const float* bk = (const float*)d_in[4];
    float* out = (float*)d_out;

    void *pqh, *pql, *pkh, *pkl, *pqf, *pkf;
    cudaGetSymbolAddress(&pqh, d_Qh);
    cudaGetSymbolAddress(&pql, d_Ql);
    cudaGetSymbolAddress(&pkh, d_Kh);
    cudaGetSymbolAddress(&pkl, d_Kl);
    cudaGetSymbolAddress(&pqf, d_Qf);
    cudaGetSymbolAddress(&pkf, d_Kf);

    // 1) projections -> fp32 + bf16 hi/lo splits
    dim3 gProj(HID / BN, ROWS / BM, 1);
    proj_kernel<<<gProj, 256>>>(x, Wq, bq, (float*)pqf,
                                (__nv_bfloat16*)pqh, (__nv_bfloat16*)pql);
    proj_kernel<<<gProj, 256>>>(x, Wk, bk, (float*)pkf,
                                (__nv_bfloat16*)pkh, (__nv_bfloat16*)pkl);

    // 2) scores via mma.sync bf16 (3-pass compensated)
    dim3 gS(NN / 128, NN / 128, BATCH);
    scores_kernel<<<gS, 256>>>();

    // 3) approx (m, Z) + top-16 candidates (single pass)
    rowtopk_kernel<<<ROWS, 256>>>();

    // 4) fp32 sequential-k rescoring (R1-matching arithmetic) + top-8 pick
    rescore_kernel<<<ROWS / 8, 256>>>();

    // 5) zero output, 6) symmetric sparse scatter
    zero_kernel<<<((size_t)BATCH * NN * NN / 4) / 256, 256>>>(out);
    scatter_kernel<<<(ROWS * KNN + 255) / 256, 256>>>(out);
}

// round 7
// speedup vs baseline: 1.6733x; 1.6733x over previous
#include <cuda_runtime.h>
#include <cuda_bf16.h>
#include <cstdint>

#define HID   256
#define NN    4096
#define BATCH 4
#define ROWS  (BATCH*NN)   // 16384
#define KNN   8
#define NCAND 16

// ---- scratch (static device globals; no runtime allocation) ----
__device__ __nv_bfloat16 d_Qh[(size_t)ROWS * HID];
__device__ __nv_bfloat16 d_Kh[(size_t)ROWS * HID];
__device__ float d_Qf[(size_t)ROWS * HID];
__device__ float d_Kf[(size_t)ROWS * HID];
__device__ float d_Sg[(size_t)BATCH * NN * NN];         // 268 MB
__device__ int   d_C16[ROWS * NCAND];
__device__ float d_Mv[ROWS];
__device__ float d_Zv[ROWS];
__device__ float d_TopV[ROWS * KNN];
__device__ int   d_TopI[ROWS * KNN];

typedef unsigned long long u64;

// ============================================================================
// PTX helpers (all sm_80-baseline)
// ============================================================================
__device__ __forceinline__ uint32_t smem_u32(const void* p) {
    uint32_t a;
    asm("{ .reg .u64 t; cvta.to.shared.u64 t, %1; cvt.u32.u64 %0, t; }" : "=r"(a) : "l"(p));
    return a;
}
__device__ __forceinline__ void cp16(uint32_t dst, const void* src) {
    asm volatile("cp.async.cg.shared.global [%0], [%1], 16;" :: "r"(dst), "l"(src));
}
__device__ __forceinline__ void ldsm4(uint32_t r[4], uint32_t addr) {
    asm volatile("ldmatrix.sync.aligned.m8n8.x4.shared.b16 {%0,%1,%2,%3}, [%4];"
                 : "=r"(r[0]), "=r"(r[1]), "=r"(r[2]), "=r"(r[3]) : "r"(addr));
}
__device__ __forceinline__ void mma_bf16(float c[4], const uint32_t a[4],
                                         uint32_t b0, uint32_t b1) {
    asm volatile(
        "mma.sync.aligned.m16n8k16.row.col.f32.bf16.bf16.f32 "
        "{%0,%1,%2,%3}, {%4,%5,%6,%7}, {%8,%9}, {%0,%1,%2,%3};"
        : "+f"(c[0]), "+f"(c[1]), "+f"(c[2]), "+f"(c[3])
        : "r"(a[0]), "r"(a[1]), "r"(a[2]), "r"(a[3]), "r"(b0), "r"(b1));
}
__device__ __forceinline__ u64 pk2(float lo, float hi) {
    u64 r;
    asm("mov.b64 %0, {%1, %2};" : "=l"(r) : "f"(lo), "f"(hi));
    return r;
}
__device__ __forceinline__ void upk2(u64 v, float& lo, float& hi) {
    asm("mov.b64 {%0, %1}, %2;" : "=f"(lo), "=f"(hi) : "l"(v));
}
__device__ __forceinline__ void fma2(u64& d, u64 a, u64 b) {
    asm("fma.rn.f32x2 %0, %1, %2, %0;" : "+l"(d) : "l"(a), "l"(b));
}
__device__ __forceinline__ uint32_t mono_f(float f) {
    uint32_t u = __float_as_uint(f);
    return (u & 0x80000000u) ? ~u : (u | 0x80000000u);
}
__device__ __forceinline__ float unmono_f(uint32_t m) {
    uint32_t u = (m & 0x80000000u) ? (m ^ 0x80000000u) : ~m;
    return __uint_as_float(u);
}

// ============================================================================
// Projection: O = x @ W^T + b -> fp32 copy + bf16 (hi only).
// ============================================================================
#define BM 128
#define BN 128
#define BK 16
#define TM 8
#define TN 8

__global__ __launch_bounds__(256, 2) void proj_kernel(
    const float* __restrict__ A, const float* __restrict__ B,
    const float* __restrict__ bias,
    float* __restrict__ Of, __nv_bfloat16* __restrict__ Oh)
{
    const int Kd = HID;
    const int tid = threadIdx.x;
    const int tx  = tid & 15;
    const int ty  = tid >> 4;
    const long bm = (long)blockIdx.y * BM;
    const long bn = (long)blockIdx.x * BN;

    __shared__ float As[2][BK][BM];
    __shared__ float Bs[2][BK][BN];

    u64 acc[TM][TN/2];
#pragma unroll
    for (int i = 0; i < TM; i++)
#pragma unroll
        for (int j = 0; j < TN/2; j++) acc[i][j] = 0ULL;

    const int lr = tid >> 1;
    const int lc = (tid & 1) * 8;
    const float* Abase = A + (bm + lr) * Kd + lc;
    const float* Bbase = B + (bn + lr) * Kd + lc;

    float4 ra0, ra1, rb0, rb1;
    ra0 = *(const float4*)(Abase);
    ra1 = *(const float4*)(Abase + 4);
    rb0 = *(const float4*)(Bbase);
    rb1 = *(const float4*)(Bbase + 4);
    {
        As[0][lc+0][lr]=ra0.x; As[0][lc+1][lr]=ra0.y; As[0][lc+2][lr]=ra0.z; As[0][lc+3][lr]=ra0.w;
        As[0][lc+4][lr]=ra1.x; As[0][lc+5][lr]=ra1.y; As[0][lc+6][lr]=ra1.z; As[0][lc+7][lr]=ra1.w;
        Bs[0][lc+0][lr]=rb0.x; Bs[0][lc+1][lr]=rb0.y; Bs[0][lc+2][lr]=rb0.z; Bs[0][lc+3][lr]=rb0.w;
        Bs[0][lc+4][lr]=rb1.x; Bs[0][lc+5][lr]=rb1.y; Bs[0][lc+6][lr]=rb1.z; Bs[0][lc+7][lr]=rb1.w;
    }
    __syncthreads();

    const int KT = Kd / BK;
    for (int kt = 0; kt < KT; ++kt) {
        const int buf = kt & 1;
        if (kt + 1 < KT) {
            const float* Ap = Abase + (kt + 1) * BK;
            const float* Bp = Bbase + (kt + 1) * BK;
            ra0 = *(const float4*)(Ap);  ra1 = *(const float4*)(Ap + 4);
            rb0 = *(const float4*)(Bp);  rb1 = *(const float4*)(Bp + 4);
        }
#pragma unroll
        for (int kk = 0; kk < BK; kk++) {
            float4 a0 = *(const float4*)&As[buf][kk][ty * TM];
            float4 a1 = *(const float4*)&As[buf][kk][ty * TM + 4];
            ulonglong2 b0 = *(const ulonglong2*)&Bs[buf][kk][tx * TN];
            ulonglong2 b1 = *(const ulonglong2*)&Bs[buf][kk][tx * TN + 4];
            u64 ad[TM] = {
                pk2(a0.x,a0.x), pk2(a0.y,a0.y), pk2(a0.z,a0.z), pk2(a0.w,a0.w),
                pk2(a1.x,a1.x), pk2(a1.y,a1.y), pk2(a1.z,a1.z), pk2(a1.w,a1.w)
            };
            u64 bd[4] = { b0.x, b0.y, b1.x, b1.y };
#pragma unroll
            for (int i = 0; i < TM; i++) {
                fma2(acc[i][0], ad[i], bd[0]);
                fma2(acc[i][1], ad[i], bd[1]);
                fma2(acc[i][2], ad[i], bd[2]);
                fma2(acc[i][3], ad[i], bd[3]);
            }
        }
        if (kt + 1 < KT) {
            const int nb = buf ^ 1;
            As[nb][lc+0][lr]=ra0.x; As[nb][lc+1][lr]=ra0.y; As[nb][lc+2][lr]=ra0.z; As[nb][lc+3][lr]=ra0.w;
            As[nb][lc+4][lr]=ra1.x; As[nb][lc+5][lr]=ra1.y; As[nb][lc+6][lr]=ra1.z; As[nb][lc+7][lr]=ra1.w;
            Bs[nb][lc+0][lr]=rb0.x; Bs[nb][lc+1][lr]=rb0.y; Bs[nb][lc+2][lr]=rb0.z; Bs[nb][lc+3][lr]=rb0.w;
            Bs[nb][lc+4][lr]=rb1.x; Bs[nb][lc+5][lr]=rb1.y; Bs[nb][lc+6][lr]=rb1.z; Bs[nb][lc+7][lr]=rb1.w;
        }
        __syncthreads();
    }

#pragma unroll
    for (int i = 0; i < TM; i++) {
        const long rrow = bm + ty * TM + i;
        const long cb = bn + tx * TN;
        float o[8];
        upk2(acc[i][0], o[0], o[1]);
        upk2(acc[i][1], o[2], o[3]);
        upk2(acc[i][2], o[4], o[5]);
        upk2(acc[i][3], o[6], o[7]);
        const float* bp = bias + cb;
#pragma unroll
        for (int j = 0; j < 8; j++) {
            float v = o[j] + bp[j];
            o[j] = v;
            Oh[rrow * HID + cb + j] = __float2bfloat16(v);
        }
        *(float4*)(Of + rrow * HID + cb)     = make_float4(o[0], o[1], o[2], o[3]);
        *(float4*)(Of + rrow * HID + cb + 4) = make_float4(o[4], o[5], o[6], o[7]);
    }
}

// ============================================================================
// Scores GEMM via mma.sync (bf16, single pass): S = Qh Kh^T / 16
// ============================================================================
#define SPITCH 40

__global__ __launch_bounds__(256) void scores_kernel()
{
    __shared__ __align__(16) __nv_bfloat16 sA[2][128 * SPITCH];
    __shared__ __align__(16) __nv_bfloat16 sB[2][128 * SPITCH];

    const int tid = threadIdx.x;
    const int wid = tid >> 5, l = tid & 31;
    const int wm = wid & 1;
    const int wn = wid >> 1;
    const long b  = blockIdx.z;
    const long bm = (long)blockIdx.y * 128;
    const long bn = (long)blockIdx.x * 128;

    const uint32_t sAu = smem_u32(sA);
    const uint32_t sBu = smem_u32(sB);

    float cacc[4][4][4];
#pragma unroll
    for (int mi = 0; mi < 4; mi++)
#pragma unroll
        for (int ni = 0; ni < 4; ni++)
#pragma unroll
            for (int e = 0; e < 4; e++) cacc[mi][ni][e] = 0.f;

    auto fill = [&](int stage, int c) {
        const int kb = c * 64;   // 32 bf16 per chunk
        const char* Ag = (const char*)(d_Qh + (b * NN + bm) * HID) + kb;
        const char* Bg = (const char*)(d_Kh + (b * NN + bn) * HID) + kb;
        const uint32_t da = sAu + stage * (128 * SPITCH * 2);
        const uint32_t db = sBu + stage * (128 * SPITCH * 2);
#pragma unroll
        for (int i = 0; i < 2; i++) {
            const int idx = tid + i * 256;
            const int row = idx >> 2, ch = idx & 3;
            cp16(da + row * (SPITCH * 2) + ch * 16, Ag + (size_t)row * (HID * 2) + ch * 16);
            cp16(db + row * (SPITCH * 2) + ch * 16, Bg + (size_t)row * (HID * 2) + ch * 16);
        }
    };

    fill(0, 0);
    asm volatile("cp.async.commit_group;" ::: "memory");
    fill(1, 1);
    asm volatile("cp.async.commit_group;" ::: "memory");

    for (int c = 0; c < 8; c++) {
        const int s = c & 1;
        if (c < 6) asm volatile("cp.async.wait_group 1;" ::: "memory");
        else       asm volatile("cp.async.wait_group 0;" ::: "memory");
        __syncthreads();

        const uint32_t ab = sAu + s * (128 * SPITCH * 2);
        const uint32_t bb = sBu + s * (128 * SPITCH * 2);

        uint32_t af[2][4][4];
        uint32_t bf[2][2][4];
        const int rA = ((l >> 3) & 1) * 8 + (l & 7);
        const int cA = (l >> 4) * 16;
        const int rB = (l >> 4) * 8 + (l & 7);
        const int cB = ((l >> 3) & 1) * 16;
#pragma unroll
        for (int kk = 0; kk < 2; kk++) {
#pragma unroll
            for (int mi = 0; mi < 4; mi++)
                ldsm4(af[kk][mi],
                      ab + (uint32_t)(wm * 64 + mi * 16 + rA) * (SPITCH * 2) + kk * 32 + cA);
#pragma unroll
            for (int bi = 0; bi < 2; bi++)
                ldsm4(bf[kk][bi],
                      bb + (uint32_t)(wn * 32 + bi * 16 + rB) * (SPITCH * 2) + kk * 32 + cB);
        }
        __syncthreads();

        if (c + 2 < 8) {
            fill(s, c + 2);
            asm volatile("cp.async.commit_group;" ::: "memory");
        }

#pragma unroll
        for (int kk = 0; kk < 2; kk++)
#pragma unroll
            for (int mi = 0; mi < 4; mi++)
#pragma unroll
                for (int ni = 0; ni < 4; ni++) {
                    const int bi = ni >> 1, p = ni & 1;
                    mma_bf16(cacc[mi][ni], af[kk][mi],
                             bf[kk][bi][p * 2], bf[kk][bi][p * 2 + 1]);
                }
    }

    const int g = l >> 2, tg = l & 3;
#pragma unroll
    for (int mi = 0; mi < 4; mi++) {
        const long r0 = bm + wm * 64 + mi * 16 + g;
        float* S0 = d_Sg + ((size_t)(b * NN + r0)) * NN + bn + wn * 32;
        float* S1 = S0 + 8 * NN;
#pragma unroll
        for (int ni = 0; ni < 4; ni++) {
            const int co = ni * 8 + tg * 2;
            float2 v0 = { cacc[mi][ni][0] * 0.0625f, cacc[mi][ni][1] * 0.0625f };
            float2 v1 = { cacc[mi][ni][2] * 0.0625f, cacc[mi][ni][3] * 0.0625f };
            *(float2*)(S0 + co) = v0;
            *(float2*)(S1 + co) = v1;
        }
    }
}

// ============================================================================
// rowtopk v3: per-thread sorted-8 (rare inserts, float threshold guard),
// REDUX-based block max, one exp pass for Z, tournament extraction of top-16.
// ============================================================================
__global__ __launch_bounds__(256) void rowtopk_kernel()
{
    const int row = blockIdx.x;
    const int tid = threadIdx.x, lid = tid & 31, wid = tid >> 5;
    const float4* S4 = (const float4*)(d_Sg + (size_t)row * NN);

    __shared__ u64 lists[8][256];     // [slot][thread] - conflict-free dumps
    __shared__ u64 wtop[8][16];       // per-warp top-16 (sorted desc)
    __shared__ uint32_t wred[8];
    __shared__ float wzs[8];

    float4 x0 = S4[tid], x1 = S4[tid + 256], x2 = S4[tid + 512], x3 = S4[tid + 768];
    float v[16] = { x0.x, x0.y, x0.z, x0.w,  x1.x, x1.y, x1.z, x1.w,
                    x2.x, x2.y, x2.z, x2.w,  x3.x, x3.y, x3.z, x3.w };

    // per-thread sorted top-8 (u64 keys), guarded by float threshold
    u64 a[8];
    const u64 KINIT = ((u64)mono_f(-3.0e38f) << 32);
#pragma unroll
    for (int k = 0; k < 8; k++) a[k] = KINIT;
    float thr = -3.0e38f;
    float m = -3.0e38f;

#pragma unroll
    for (int i = 0; i < 16; i++) {
        const float val = v[i];
        m = fmaxf(m, val);
        if (val >= thr) {
            const int gi = (i >> 2) * 1024 + tid * 4 + (i & 3);
            const u64 key = ((u64)mono_f(val) << 32) | (unsigned)(4095 - gi);
            if (key > a[7]) {
                a[7] = key;
#pragma unroll
                for (int t = 7; t > 0; t--)
                    if (a[t] > a[t-1]) { u64 tmp = a[t]; a[t] = a[t-1]; a[t-1] = tmp; }
                thr = unmono_f((uint32_t)(a[7] >> 32));
            }
        }
    }

    // block max via REDUX
    {
        const uint32_t mk = __reduce_max_sync(0xFFFFFFFFu, mono_f(m));
        if (lid == 0) wred[wid] = mk;
    }
    __syncthreads();
    if (wid == 0) {
        uint32_t t = (lid < 8) ? wred[lid] : 0u;
        t = __reduce_max_sync(0xFFFFFFFFu, t);
        if (lid == 0) wred[0] = t;
    }
    __syncthreads();
    m = unmono_f(wred[0]);

    // Z with fixed m
    float z = 0.f;
#pragma unroll
    for (int i = 0; i < 16; i++) z += __expf(v[i] - m);
#pragma unroll
    for (int o = 16; o; o >>= 1) z += __shfl_xor_sync(0xFFFFFFFFu, z, o);
    if (lid == 0) wzs[wid] = z;

    // dump candidate lists
#pragma unroll
    for (int k = 0; k < 8; k++) lists[k][tid] = a[k];
    __syncwarp();

    // per-warp tournament: top-16 of the warp's 32 sorted-8 lists
    {
        int head = 0;
        u64 cur = a[0];
        for (int r = 0; r < 16; r++) {
            const uint32_t hi = (uint32_t)(cur >> 32);
            const uint32_t win = __reduce_max_sync(0xFFFFFFFFu, hi);
            const uint32_t ball = __ballot_sync(0xFFFFFFFFu, hi == win);
            const int wl = __ffs(ball) - 1;
            if (lid == wl) {
                wtop[wid][r] = cur;
                head++;
                cur = (head < 8) ? lists[head][tid] : 0ULL;
            }
        }
    }
    __syncthreads();

    // final: warp 0 merges the 8 sorted-16 lists
    if (wid == 0) {
        int h = 0;
        u64 cur = (lid < 8) ? wtop[lid][0] : 0ULL;
        for (int r = 0; r < 16; r++) {
            const uint32_t hi = (uint32_t)(cur >> 32);
            const uint32_t win = __reduce_max_sync(0xFFFFFFFFu, hi);
            const uint32_t ball = __ballot_sync(0xFFFFFFFFu, hi == win);
            const int wl = __ffs(ball) - 1;
            if (lid == wl) {
                d_C16[row * NCAND + r] = 4095 - (int)(cur & 0xFFFFFFFFu);
                h++;
                cur = (h < 16) ? wtop[lid][h] : 0ULL;
            }
        }
        if (lid == 0) {
            float Z = 0.f;
#pragma unroll
            for (int w = 0; w < 8; w++) Z += wzs[w];
            d_Mv[row] = m;
            d_Zv[row] = Z;
        }
    }
}

// ============================================================================
// rescore: fp32 SEQUENTIAL-k fma chain (bit-matched to R1/ref arithmetic).
// One warp per row; lanes 0..15 each score one candidate. (R6-proven.)
// ============================================================================
__global__ __launch_bounds__(256) void rescore_kernel()
{
    __shared__ float sq[8][HID];
    const int wid = threadIdx.x >> 5, lane = threadIdx.x & 31;
    const int row = blockIdx.x * 8 + wid;
    const int b = row >> 12;

    for (int i = lane; i < HID; i += 32)
        sq[wid][i] = d_Qf[(size_t)row * HID + i];
    __syncwarp();

    float s = 0.f; int j = 0;
    if (lane < NCAND) {
        j = d_C16[row * NCAND + lane];
        const float* kr = d_Kf + ((size_t)((b << 12) + j)) * HID;
        float acc = 0.f;
#pragma unroll
        for (int k = 0; k < HID; k++)
            acc = fmaf(sq[wid][k], __ldg(kr + k), acc);
        s = acc * 0.0625f;
    }

    float scs[NCAND]; int ixs[NCAND];
#pragma unroll
    for (int c = 0; c < NCAND; c++) {
        scs[c] = __shfl_sync(0xFFFFFFFFu, s, c);
        ixs[c] = __shfl_sync(0xFFFFFFFFu, j, c);
    }

    if (lane == 0) {
        u64 key[NCAND];
#pragma unroll
        for (int c = 0; c < NCAND; c++)
            key[c] = ((u64)mono_f(scs[c]) << 32) | (unsigned)(4095 - ixs[c]);
        for (int i = 1; i < NCAND; i++) {
            u64 kv = key[i];
            int jj = i;
            while (jj > 0 && key[jj-1] < kv) { key[jj] = key[jj-1]; jj--; }
            key[jj] = kv;
        }
        const float m = d_Mv[row], z = d_Zv[row];
        float ev[KNN]; int oi[KNN]; float E8 = 0.f;
#pragma unroll
        for (int k = 0; k < KNN; k++) {
            const uint32_t mv = (uint32_t)(key[k] >> 32);
            const uint32_t u = (mv & 0x80000000u) ? (mv ^ 0x80000000u) : ~mv;
            const float sv = __uint_as_float(u);
            oi[k] = 4095 - (int)(key[k] & 0xFFFFFFFFu);
            ev[k] = __expf(sv - m);
            E8 += ev[k];
        }
        const float inv = 1.0f / (E8 + 1e-6f * z);
#pragma unroll
        for (int k = 0; k < KNN; k++) {
            d_TopV[row * KNN + k] = ev[k] * inv;
            d_TopI[row * KNN + k] = oi[k];
        }
    }
}

// ============================================================================
// Output: zero then symmetric sparse scatter (0.5*(A + A^T))
// ============================================================================
__global__ void zero_kernel(float* __restrict__ out)
{
    const size_t i = (size_t)blockIdx.x * blockDim.x + threadIdx.x;
    ((float4*)out)[i] = make_float4(0.f, 0.f, 0.f, 0.f);
}

__global__ void scatter_kernel(float* __restrict__ out)
{
    const int t = blockIdx.x * blockDim.x + threadIdx.x;
    if (t >= ROWS * KNN) return;
    const int row = t / KNN;
    const int b = row >> 12;
    const int i = row & (NN - 1);
    const int j = d_TopI[t];
    const float v = 0.5f * d_TopV[t];
    float* base = out + (size_t)b * NN * NN;
    atomicAdd(base + (size_t)i * NN + j, v);
    atomicAdd(base + (size_t)j * NN + i, v);
}

// ============================================================================
extern "C" void kernel_launch(void* const* d_in, const int* in_sizes, int n_in,
                              void* d_out, int out_size)
{
    const float* x  = (const float*)d_in[0];
    const float* Wq = (const float*)d_in[1];
    const float* bq = (const float*)d_in[2];
    const float* Wk = (const float*)d_in[3];
    const float* bk = (const float*)d_in[4];
    float* out = (float*)d_out;

    void *pqh, *pkh, *pqf, *pkf;
    cudaGetSymbolAddress(&pqh, d_Qh);
    cudaGetSymbolAddress(&pkh, d_Kh);
    cudaGetSymbolAddress(&pqf, d_Qf);
    cudaGetSymbolAddress(&pkf, d_Kf);

    // 1) projections -> fp32 + bf16
    dim3 gProj(HID / BN, ROWS / BM, 1);
    proj_kernel<<<gProj, 256>>>(x, Wq, bq, (float*)pqf, (__nv_bfloat16*)pqh);
    proj_kernel<<<gProj, 256>>>(x, Wk, bk, (float*)pkf, (__nv_bfloat16*)pkh);

    // 2) scores via mma.sync bf16 (single pass)
    dim3 gS(NN / 128, NN / 128, BATCH);
    scores_kernel<<<gS, 256>>>();

    // 3) approx (m, Z) + top-16 candidates (single pass, tournament)
    rowtopk_kernel<<<ROWS, 256>>>();

    // 4) fp32 sequential-k rescoring + exact top-8 pick
    rescore_kernel<<<ROWS / 8, 256>>>();

    // 5) zero output, 6) symmetric sparse scatter
    zero_kernel<<<((size_t)BATCH * NN * NN / 4) / 256, 256>>>(out);
    scatter_kernel<<<(ROWS * KNN + 255) / 256, 256>>>(out);
}